// round 9
// baseline (speedup 1.0000x reference)
#include <cuda_runtime.h>

// SmallRNN: h_t = tanh(x_t * w_ih^T + b_ih + h_{t-1} * w_hh^T + b_hh), out = h_T @ fc_w^T + fc_b
// Shapes: x [B=4096, T=2048, I=1], w_ih [8,1], w_hh [8,8], b_* [8], fc_w [1,8], fc_b [1]
//
// R7: 8 lanes per batch element; smem exchange (volatile-asm STS -> 2x LDS.128,
// ordering via asm-volatile mutual order; smem touched ONLY by asm so no memory
// clobbers needed). tanh.approx for first T-64 steps, exact ex2+rcp tail
// (recurrence contracts; proven rel_err ~1.8e-7). Main loop peeled: no bounds
// check in the hot loop.

#define TBLOCK 256
#define EXACT_TAIL 64

__device__ __forceinline__ float ex2f(float x) {
    float y; asm("ex2.approx.f32 %0, %1;" : "=f"(y) : "f"(x)); return y;
}
__device__ __forceinline__ float rcpf(float x) {
    float y; asm("rcp.approx.f32 %0, %1;" : "=f"(y) : "f"(x)); return y;
}
__device__ __forceinline__ float tanhf_approx(float x) {
    float y; asm("tanh.approx.f32 %0, %1;" : "=f"(y) : "f"(x)); return y;
}

template <bool EXACT>
__device__ __forceinline__ float rnn_step(float h, float xv,
                                          unsigned own_addr, unsigned vec_addr,
                                          const float w[8], float Bj, float wih) {
    // publish own h, then fetch the group's 8 values. asm volatile statements
    // are ordered among themselves; smem is accessed only through these asms,
    // so no "memory" clobber is needed (keeps the compiler free to schedule
    // surrounding FMAs/prefetch loads tightly).
    asm volatile("st.shared.f32 [%0], %1;" :: "r"(own_addr), "f"(h));
    float v0, v1, v2, v3, v4, v5, v6, v7;
    asm volatile("ld.shared.v4.f32 {%0,%1,%2,%3}, [%4];"
                 : "=f"(v0), "=f"(v1), "=f"(v2), "=f"(v3)
                 : "r"(vec_addr));
    asm volatile("ld.shared.v4.f32 {%0,%1,%2,%3}, [%4];"
                 : "=f"(v4), "=f"(v5), "=f"(v6), "=f"(v7)
                 : "r"(vec_addr + 16u));
    // 4-way split FMA tree, then combine; x-term and bias are off-chain
    float a = fmaf(xv, wih, Bj);
    a = fmaf(v0, w[0], a);
    float b = v1 * w[1];
    float cc = v2 * w[2];
    float d = v3 * w[3];
    a  = fmaf(v4, w[4], a);
    b  = fmaf(v5, w[5], b);
    cc = fmaf(v6, w[6], cc);
    d  = fmaf(v7, w[7], d);
    float s = (a + b) + (cc + d);
    if (EXACT) {
        const float c2 = 2.8853900817779268f; // 2*log2(e)
        float e = ex2f(c2 * s);
        float r = rcpf(e + 1.0f);
        return fmaf(-2.0f, r, 1.0f); // tanh(s) = 1 - 2*sigmoid(-2s)
    } else {
        return tanhf_approx(s);
    }
}

__global__ void __launch_bounds__(TBLOCK)
SmallRNN_kernel(const float* __restrict__ x,
                const float* __restrict__ w_ih,
                const float* __restrict__ w_hh,
                const float* __restrict__ b_ih,
                const float* __restrict__ b_hh,
                const float* __restrict__ fc_w,
                const float* __restrict__ fc_b,
                float* __restrict__ out,
                int B, int T) {
    __shared__ float sh[TBLOCK];

    int tx = threadIdx.x;
    int gtid = blockIdx.x * TBLOCK + tx;
    int b_raw = gtid >> 3;     // batch element
    int j = gtid & 7;          // hidden unit owned by this lane
    int b = (b_raw < B) ? b_raw : (B - 1);  // keep lanes active

    unsigned own_addr = (unsigned)__cvta_generic_to_shared(sh + tx);
    unsigned vec_addr = (unsigned)__cvta_generic_to_shared(sh + (tx & ~7));

    float w[8];
#pragma unroll
    for (int k = 0; k < 8; k++) w[k] = w_hh[j * 8 + k];
    float Bj  = b_ih[j] + b_hh[j];
    float wih = w_ih[j];

    const float* xp = x + (size_t)b * (size_t)T;
    float h = 0.0f; // h0 = 0

    int Tmain = T - EXACT_TAIL;
    if (Tmain < 0) Tmain = 0;
    int Tm = Tmain & ~7;

    if (((unsigned long long)xp & 15ull) == 0ull && Tm >= 16) {
        float4 xa = *(const float4*)(xp);
        float4 xb_ = *(const float4*)(xp + 4);
        // hot loop: unconditional prefetch, no bounds check
        int t = 0;
        for (; t + 16 <= Tm; t += 8) {
            float4 xn0 = *(const float4*)(xp + t + 8);
            float4 xn1 = *(const float4*)(xp + t + 12);
            h = rnn_step<false>(h, xa.x,  own_addr, vec_addr, w, Bj, wih);
            h = rnn_step<false>(h, xa.y,  own_addr, vec_addr, w, Bj, wih);
            h = rnn_step<false>(h, xa.z,  own_addr, vec_addr, w, Bj, wih);
            h = rnn_step<false>(h, xa.w,  own_addr, vec_addr, w, Bj, wih);
            h = rnn_step<false>(h, xb_.x, own_addr, vec_addr, w, Bj, wih);
            h = rnn_step<false>(h, xb_.y, own_addr, vec_addr, w, Bj, wih);
            h = rnn_step<false>(h, xb_.z, own_addr, vec_addr, w, Bj, wih);
            h = rnn_step<false>(h, xb_.w, own_addr, vec_addr, w, Bj, wih);
            xa  = xn0;
            xb_ = xn1;
        }
        // final prefetched block (t = Tm-8)
        h = rnn_step<false>(h, xa.x,  own_addr, vec_addr, w, Bj, wih);
        h = rnn_step<false>(h, xa.y,  own_addr, vec_addr, w, Bj, wih);
        h = rnn_step<false>(h, xa.z,  own_addr, vec_addr, w, Bj, wih);
        h = rnn_step<false>(h, xa.w,  own_addr, vec_addr, w, Bj, wih);
        h = rnn_step<false>(h, xb_.x, own_addr, vec_addr, w, Bj, wih);
        h = rnn_step<false>(h, xb_.y, own_addr, vec_addr, w, Bj, wih);
        h = rnn_step<false>(h, xb_.z, own_addr, vec_addr, w, Bj, wih);
        h = rnn_step<false>(h, xb_.w, own_addr, vec_addr, w, Bj, wih);
    } else {
        Tm = 0;
    }
    // remainder of the approx region (unaligned fallback or Tmain%8)
    for (int t = Tm; t < Tmain; t++) {
        h = rnn_step<false>(h, xp[t], own_addr, vec_addr, w, Bj, wih);
    }
    // exact tail
    for (int t = Tmain; t < T; t++) {
        h = rnn_step<true>(h, xp[t], own_addr, vec_addr, w, Bj, wih);
    }

    // out[b] = sum_j h_j * fc_w[j] + fc_b
    float v = h * fc_w[j];
    v += __shfl_xor_sync(0xffffffffu, v, 4, 8);
    v += __shfl_xor_sync(0xffffffffu, v, 2, 8);
    v += __shfl_xor_sync(0xffffffffu, v, 1, 8);
    if (j == 0 && b_raw < B) out[b] = v + fc_b[0];
}

extern "C" void kernel_launch(void* const* d_in, const int* in_sizes, int n_in,
                              void* d_out, int out_size) {
    const float* x    = (const float*)d_in[0];
    const float* w_ih = (const float*)d_in[1];
    const float* w_hh = (const float*)d_in[2];
    const float* b_ih = (const float*)d_in[3];
    const float* b_hh = (const float*)d_in[4];
    const float* fc_w = (const float*)d_in[5];
    const float* fc_b = (const float*)d_in[6];
    float* out = (float*)d_out;

    int B = out_size;                 // O = 1
    int T = in_sizes[0] / B;          // I = 1
    int threads = B * 8;
    int grid = (threads + TBLOCK - 1) / TBLOCK;
    SmallRNN_kernel<<<grid, TBLOCK>>>(x, w_ih, w_hh, b_ih, b_hh, fc_w, fc_b,
                                      out, B, T);
}